// round 11
// baseline (speedup 1.0000x reference)
#include <cuda_runtime.h>
#include <cuda_bf16.h>
#include <mma.h>
#include <cstddef>
#include <cstdint>

using namespace nvcuda;

// Problem constants
#define N_TOK   32768
#define DIM     128
#define KCODES  1024
#define NCB     8
#define M_TILE  128
#define TPB     256
#define GRID_MAIN (N_TOK / M_TILE)    // 256
#define NCHUNK  256                   // 32-code chunks across all codebooks

// Device scratch (no allocations allowed)
__device__ float g_wn[NCB * KCODES];
__device__ float g_wnmax[NCB];
__device__ float g_part[GRID_MAIN];
__device__ __align__(16) __nv_bfloat16 g_cb16[(size_t)NCB * KCODES * DIM];

// smem offsets (all 16B aligned); strides: res 129 f32, A/B 136 bf16, C 36 f32
#define SO_RES   0         // float [128][129]            66048 B
#define SO_A     66048     // bf16  [128][136]            34816 B
#define SO_B     100864    // bf16  2 x [32][136]         17408 B
#define SO_C     118272    // float 8 x [16][36]          18432 B
#define SO_WN    136704    // float [1024]                 4096 B
#define SO_CODES 140800    // int   [8][128]               4096 B
#define SO_RED   144896    // float [256]                  1024 B
#define SMEM_REQ 145920
#define BBUF     8704      // one B buffer: 32*136*2

extern __shared__ char smraw[];

// ---------------------------------------------------------------------------
__device__ __forceinline__ uint32_t smem_u32(const void* p) {
    uint32_t a;
    asm("{ .reg .u64 t; cvta.to.shared.u64 t, %1; cvt.u32.u64 %0, t; }"
        : "=r"(a) : "l"(p));
    return a;
}
__device__ __forceinline__ void cp_async16(uint32_t dst, const void* src) {
    asm volatile("cp.async.cg.shared.global [%0], [%1], 16;\n" :: "r"(dst), "l"(src));
}
#define CP_COMMIT() asm volatile("cp.async.commit_group;\n" ::: "memory")
#define CP_WAIT(n)  asm volatile("cp.async.wait_group %0;\n" :: "n"(n) : "memory")

// ---------------------------------------------------------------------------
// Kernel 1: ||w||^2 per code (frozen chain)
// ---------------------------------------------------------------------------
__global__ void wnorm_kernel(const float* __restrict__ cb) {
    int gwarp = (blockIdx.x * blockDim.x + threadIdx.x) >> 5;
    int lane  = threadIdx.x & 31;
    if (gwarp >= NCB * KCODES) return;
    const float* w = cb + (size_t)gwarp * DIM;
    float s = 0.f;
    #pragma unroll
    for (int i = 0; i < DIM / 32; ++i) { float v = w[lane + 32 * i]; s = __fmaf_rn(v, v, s); }
    #pragma unroll
    for (int o = 16; o > 0; o >>= 1) s = __fadd_rn(s, __shfl_xor_sync(0xFFFFFFFFu, s, o));
    if (lane == 0) g_wn[gwarp] = s;
}

// Kernel 1b: per-codebook max ||w||^2
__global__ void wnmax_kernel() {
    __shared__ float red[256];
    int c = blockIdx.x, t = threadIdx.x;
    float mx = 0.f;
    for (int e = t; e < KCODES; e += 256) mx = fmaxf(mx, g_wn[c * KCODES + e]);
    red[t] = mx; __syncthreads();
    for (int s = 128; s > 0; s >>= 1) { if (t < s) red[t] = fmaxf(red[t], red[t + s]); __syncthreads(); }
    if (t == 0) g_wnmax[c] = red[0];
}

// Kernel 1c: codebook fp32 -> bf16 (row-major, same layout)
__global__ void cb16_kernel(const float* __restrict__ cb) {
    int i = blockIdx.x * blockDim.x + threadIdx.x;
    if (i < NCB * KCODES * DIM) g_cb16[i] = __float2bfloat16(cb[i]);
}

// ---------------------------------------------------------------------------
// stage one 32-code chunk: g_cb16 rows -> Bs[code][dim] bf16 (stride 136)
// ---------------------------------------------------------------------------
__device__ __forceinline__ void stage_chunk(char* S, int g, int tid) {
    uint32_t dstb = smem_u32(S + SO_B + (g & 1) * BBUF);
    const char* src = (const char*)g_cb16 + (size_t)g * 32 * DIM * 2;   // 8192B
    #pragma unroll
    for (int r = 0; r < 2; ++r) {
        int e = tid + r * TPB;          // 0..511 x 16B
        int code = e >> 4, q = e & 15;
        cp_async16(dstb + code * 272 + q * 16, src + e * 16);
    }
    CP_COMMIT();
}

// ---------------------------------------------------------------------------
// Kernel 2: main. Block = 128 tokens, 8 warps; warp owns 16 tokens.
// bf16 HMMA prune (top-8 per lane, lane pairs split 32 codes) + exact
// fp32 rescore with the FROZEN validated chain -> codes bit-exact.
// Fallback is WARP-UNIFORM (ballot) so all shuffles execute converged.
// ---------------------------------------------------------------------------
__global__ __launch_bounds__(TPB) void rvq_main(
    const float* __restrict__ emb, const float* __restrict__ cb,
    float* __restrict__ out_codes, float* __restrict__ out_quant)
{
    char* S = smraw;
    float*          resf    = reinterpret_cast<float*>(S + SO_RES);
    __nv_bfloat16*  As      = reinterpret_cast<__nv_bfloat16*>(S + SO_A);
    float*          wn_s    = reinterpret_cast<float*>(S + SO_WN);
    int*            codes_s = reinterpret_cast<int*>(S + SO_CODES);
    float*          red     = reinterpret_cast<float*>(S + SO_RED);

    const int tid  = threadIdx.x;
    const int wid  = tid >> 5;
    const int lane = tid & 31;
    const int n0   = blockIdx.x * M_TILE;
    float* Cw = reinterpret_cast<float*>(S + SO_C) + wid * (16 * 36);

    stage_chunk(S, 0, tid);   // prefetch chunk 0

    // residual <- emb + rr (frozen chain); lane pair (r, r+16) holds rr of token r
    float rr_own = 0.f;
    for (int t2 = 0; t2 < 16; ++t2) {
        int m = wid * 16 + t2;
        const float* er = emb + (size_t)(n0 + m) * DIM;
        float* rw = resf + m * 129;
        float s = 0.f;
        #pragma unroll
        for (int q = 0; q < DIM / 32; ++q) {
            int d = lane + 32 * q;
            float v = er[d]; rw[d] = v; s = __fmaf_rn(v, v, s);
        }
        #pragma unroll
        for (int o = 16; o > 0; o >>= 1) s = __fadd_rn(s, __shfl_xor_sync(0xFFFFFFFFu, s, o));
        if ((lane & 15) == t2) rr_own = s;
    }

    float lsum = 0.f;

    for (int c = 0; c < NCB; ++c) {
        const float* cbc = cb + (size_t)c * KCODES * DIM;

        __syncthreads();   // prev-cb update/quant readers done
        for (int e = tid; e < KCODES; e += TPB) wn_s[e] = g_wn[c * KCODES + e];
        for (int e = tid; e < M_TILE * DIM; e += TPB) {
            int m = e >> 7, d = e & 127;
            As[m * 136 + d] = __float2bfloat16(resf[m * 129 + d]);
        }
        __syncthreads();   // A + wn visible

        wmma::fragment<wmma::matrix_a, 16, 16, 16, __nv_bfloat16, wmma::row_major> af[8];
        #pragma unroll
        for (int k = 0; k < 8; ++k)
            wmma::load_matrix_sync(af[k], As + wid * 16 * 136 + k * 16, 136);

        float cu[8]; int ck[8];
        #pragma unroll
        for (int s = 0; s < 8; ++s) { cu[s] = 1e30f; ck[s] = 0; }

        const int r    = lane & 15;
        const int half = lane >> 4;

        for (int t = 0; t < 32; ++t) {
            int g = c * 32 + t;
            __syncthreads();                       // all warps done with buffer (g+1)&1
            if (g + 1 < NCHUNK) { stage_chunk(S, g + 1, tid); CP_WAIT(1); }
            else                { CP_WAIT(0); }
            __syncthreads();                       // chunk g visible

            const __nv_bfloat16* Bs =
                reinterpret_cast<const __nv_bfloat16*>(S + SO_B + (g & 1) * BBUF);

            wmma::fragment<wmma::accumulator, 16, 16, 16, float> acc0, acc1;
            wmma::fill_fragment(acc0, 0.0f);
            wmma::fill_fragment(acc1, 0.0f);
            #pragma unroll
            for (int k = 0; k < 8; ++k) {
                wmma::fragment<wmma::matrix_b, 16, 16, 16, __nv_bfloat16, wmma::col_major> b0, b1;
                wmma::load_matrix_sync(b0, Bs + k * 16, 136);
                wmma::load_matrix_sync(b1, Bs + 16 * 136 + k * 16, 136);
                wmma::mma_sync(acc0, af[k], b0, acc0);
                wmma::mma_sync(acc1, af[k], b1, acc1);
            }
            wmma::store_matrix_sync(Cw,      acc0, 36, wmma::mem_row_major);
            wmma::store_matrix_sync(Cw + 16, acc1, 36, wmma::mem_row_major);
            __syncwarp();

            int kb = t * 32 + half * 16;           // within-cb code base for this lane
            const float* crow = Cw + r * 36 + half * 16;
            #pragma unroll
            for (int cc = 0; cc < 16; ++cc) {
                float v = __fmaf_rn(-2.0f, crow[cc], wn_s[kb + cc]);
                if (v < cu[7]) {
                    int s = 7;
                    #pragma unroll
                    for (int z = 0; z < 7; ++z)
                        if (s > 0 && v < cu[s - 1]) { cu[s] = cu[s - 1]; ck[s] = ck[s - 1]; --s; }
                    cu[s] = v; ck[s] = kb + cc;
                }
            }
            __syncwarp();                          // scan done before Cw rewritten
        }

        // exact rescore: each lane rescores its 8 candidates (frozen chain)
        const float rr = rr_own;
        const float* rrow = resf + (wid * 16 + r) * 129;
        float bestU = 1e30f; int bestK = 0x7fffffff;
        #pragma unroll
        for (int s = 0; s < 8; ++s) {
            int k = ck[s];
            const float4* w4 = reinterpret_cast<const float4*>(cbc + (size_t)k * DIM);
            float lo = 0.f, hi = 0.f;
            #pragma unroll 8
            for (int q = 0; q < 32; ++q) {
                float4 w = __ldg(w4 + q);
                lo = __fmaf_rn(rrow[4 * q],     w.x, lo);
                hi = __fmaf_rn(rrow[4 * q + 1], w.y, hi);
                lo = __fmaf_rn(rrow[4 * q + 2], w.z, lo);
                hi = __fmaf_rn(rrow[4 * q + 3], w.w, hi);
            }
            float m_ = __fadd_rn(lo, hi);
            float u  = __fadd_rn(__fmaf_rn(-2.0f, m_, rr), wn_s[k]);
            if (u < bestU || (u == bestU && k < bestK)) { bestU = u; bestK = k; }
        }
        // merge lane pair (same token) + prune-soundness threshold
        float thr = fminf(cu[7], __shfl_xor_sync(0xFFFFFFFFu, cu[7], 16));
        {
            float ou = __shfl_xor_sync(0xFFFFFFFFu, bestU, 16);
            int   ok = __shfl_xor_sync(0xFFFFFFFFu, bestK, 16);
            if (ou < bestU || (ou == bestU && ok < bestK)) { bestU = ou; bestK = ok; }
        }
        float E = __fmaf_rn(0.017f, sqrtf(rr * g_wnmax[c]), 1e-4f);
        bool need = !((rr + thr) - E > bestU + 2e-5f);
        // WARP-UNIFORM fallback: if any token of this warp needs it, all 32
        // lanes run the exact full scan (converged shuffles -> no deadlock).
        if (__ballot_sync(0xFFFFFFFFu, need)) {
            float bU = 1e30f; int bK = 0;
            int k0 = half * 512;
            for (int k = k0; k < k0 + 512; ++k) {
                const float4* w4 = reinterpret_cast<const float4*>(cbc + (size_t)k * DIM);
                float lo = 0.f, hi = 0.f;
                #pragma unroll 4
                for (int q = 0; q < 32; ++q) {
                    float4 w = __ldg(w4 + q);
                    lo = __fmaf_rn(rrow[4 * q],     w.x, lo);
                    hi = __fmaf_rn(rrow[4 * q + 1], w.y, hi);
                    lo = __fmaf_rn(rrow[4 * q + 2], w.z, lo);
                    hi = __fmaf_rn(rrow[4 * q + 3], w.w, hi);
                }
                float m_ = __fadd_rn(lo, hi);
                float u  = __fadd_rn(__fmaf_rn(-2.0f, m_, rr), wn_s[k]);
                if (u < bU) { bU = u; bK = k; }        // ascending k: first-min kept
            }
            float ou = __shfl_xor_sync(0xFFFFFFFFu, bU, 16);
            int   ok = __shfl_xor_sync(0xFFFFFFFFu, bK, 16);
            if (ou < bU || (ou == bU && ok < bK)) { bU = ou; bK = ok; }
            if (need) { bestU = bU; bestK = bK; }   // exact result for flagged tokens
        }
        if (lane < 16) {
            int m = wid * 16 + lane;
            codes_s[c * M_TILE + m] = bestK;
            out_codes[(size_t)(n0 + m) * NCB + c] = (float)bestK;
        }

        __syncthreads();   // codes_s complete; rescore reads of resf done

        // residual update (exact elementwise chain) + loss
        for (int e = tid; e < M_TILE * DIM; e += TPB) {
            int m = e >> 7, d = e & 127;
            float w = cbc[(size_t)codes_s[c * M_TILE + m] * DIM + d];
            float rv = __fadd_rn(resf[m * 129 + d], -w);
            resf[m * 129 + d] = rv;
            lsum += rv * rv;
        }
        __syncthreads();   // updated residual visible

        // rr for next step (frozen warp-collective chain)
        for (int t2 = 0; t2 < 16; ++t2) {
            const float* rw = resf + (wid * 16 + t2) * 129;
            float s = 0.f;
            #pragma unroll
            for (int q = 0; q < DIM / 32; ++q) { float v = rw[lane + 32 * q]; s = __fmaf_rn(v, v, s); }
            #pragma unroll
            for (int o = 16; o > 0; o >>= 1) s = __fadd_rn(s, __shfl_xor_sync(0xFFFFFFFFu, s, o));
            if ((lane & 15) == t2) rr_own = s;
        }
    }

    // quantized: q = sum_c w[idx_c] (reference add chain from 0); STE
    __syncthreads();
    for (int e = tid; e < M_TILE * DIM; e += TPB) {
        int m = e >> 7, d = e & 127;
        float q = cb[(size_t)codes_s[m] * DIM + d];
        #pragma unroll
        for (int c = 1; c < NCB; ++c)
            q = __fadd_rn(q, cb[(size_t)c * KCODES * DIM
                               + (size_t)codes_s[c * M_TILE + m] * DIM + d]);
        size_t g = (size_t)(n0 + m) * DIM + d;
        float e0 = emb[g];
        out_quant[g] = __fadd_rn(e0, __fadd_rn(q, -e0));
    }

    // deterministic block loss reduction
    red[tid] = lsum;
    __syncthreads();
    for (int s = TPB / 2; s > 0; s >>= 1) {
        if (tid < s) red[tid] += red[tid + s];
        __syncthreads();
    }
    if (tid == 0) g_part[blockIdx.x] = red[0];
}

// ---------------------------------------------------------------------------
__global__ void loss_final(float* __restrict__ out_loss) {
    __shared__ float red[GRID_MAIN];
    int t = threadIdx.x;
    red[t] = g_part[t];
    __syncthreads();
    for (int s = GRID_MAIN / 2; s > 0; s >>= 1) {
        if (t < s) red[t] += red[t + s];
        __syncthreads();
    }
    if (t == 0)
        out_loss[0] = red[0] * (1.0f / ((float)N_TOK * (float)DIM * (float)NCB));
}

// ---------------------------------------------------------------------------
extern "C" void kernel_launch(void* const* d_in, const int* in_sizes, int n_in,
                              void* d_out, int out_size) {
    const float* emb = (const float*)d_in[0];   // [8,4096,128] f32
    const float* cb  = (const float*)d_in[1];   // [8,1024,128] f32

    float* out_codes = (float*)d_out;                         // 32768*8
    float* out_quant = out_codes + (size_t)N_TOK * NCB;       // 32768*128
    float* out_loss  = out_quant + (size_t)N_TOK * DIM;       // 1

    cudaFuncSetAttribute(rvq_main, cudaFuncAttributeMaxDynamicSharedMemorySize, SMEM_REQ);

    wnorm_kernel<<<(NCB * KCODES) / 8, 256>>>(cb);
    wnmax_kernel<<<NCB, 256>>>();
    cb16_kernel<<<(NCB * KCODES * DIM + 255) / 256, 256>>>(cb);
    rvq_main<<<GRID_MAIN, TPB, SMEM_REQ>>>(emb, cb, out_codes, out_quant);
    loss_final<<<1, GRID_MAIN>>>(out_loss);
}